// round 11
// baseline (speedup 1.0000x reference)
#include <cuda_runtime.h>
#include <math.h>

typedef unsigned long long ull;

// ---------------------------------------------------------------------------
// Packed f32x2 helpers (convB family only — measured fastest for L4/L5)
// ---------------------------------------------------------------------------
__device__ __forceinline__ ull pk2(float lo, float hi) {
    ull r; asm("mov.b64 %0, {%1, %2};" : "=l"(r) : "f"(lo), "f"(hi)); return r;
}
__device__ __forceinline__ void upk2(ull v, float& lo, float& hi) {
    asm("mov.b64 {%0, %1}, %2;" : "=f"(lo), "=f"(hi) : "l"(v));
}
__device__ __forceinline__ void fma2(ull& d, ull a, ull b) {
    asm("fma.rn.f32x2 %0, %1, %2, %0;" : "+l"(d) : "l"(a), "l"(b));
}

// ---------------------------------------------------------------------------
// Intermediate activation buffers (device globals — no allocation allowed).
// ---------------------------------------------------------------------------
__device__ float g_a1[38880000];   // 256*3*15^4
__device__ float g_a2[15925248];   // 256*3*12^4
__device__ float g_a3[6718464];    // 256*4*9^4
__device__ float g_a4[1658880];    // 256*5*6^4

__host__ __device__ constexpr int slice_pitch(int s3) { return (s3 + 6) & ~1; }

// ===========================================================================
// convS: R1's proven full-row scalar conv (+bias+ReLU). Block = (b, t-chunk).
// Thread = (t_local, d, h) computes the full W row for all COUT.
// ===========================================================================
template<int CIN, int COUT, int K, int S, int TLOC, int NTHR, int MINB>
__global__ void __launch_bounds__(NTHR, MINB)
convS(const float* __restrict__ in, float* __restrict__ out,
      const float* __restrict__ w, const float* __restrict__ bias)
{
    constexpr int O = S - K + 1, TCH = O / TLOC, NST = TLOC + K - 1;
    constexpr int S2 = S * S, S3 = S2 * S, S4 = S3 * S;
    constexpr int O2 = O * O, O3 = O2 * O;
    constexpr int KW4 = K * K * K * K;
    constexpr int NW = COUT * CIN * KW4;
    constexpr int NACT = TLOC * O2;

    __shared__ float s_slice[S3];
    __shared__ float s_w[NW];

    const int bt = blockIdx.x, tchunk = bt % TCH, b = bt / TCH;
    const int t0 = tchunk * TLOC, tid = threadIdx.x;

    for (int i = tid; i < NW; i += NTHR) s_w[i] = w[i];

    const int tl = tid / O2, rem = tid - tl * O2, dd = rem / O, hh = rem - dd * O;
    const bool act = tid < NACT;

    float acc[COUT][O];
#pragma unroll
    for (int c = 0; c < COUT; c++)
#pragma unroll
        for (int r = 0; r < O; r++) acc[c][r] = 0.0f;

#pragma unroll 1
    for (int ci = 0; ci < CIN; ci++) {
#pragma unroll 1
        for (int s = 0; s < NST; s++) {
            __syncthreads();
            const float* src = in + (size_t)(b * CIN + ci) * S4 + (size_t)(t0 + s) * S3;
            for (int i = tid; i < S3; i += NTHR) s_slice[i] = src[i];
            __syncthreads();

            const int kt = s - tl;
            if (act && kt >= 0 && kt < K) {
                const float* wb = s_w + (ci * K + kt) * (K * K * K);
#pragma unroll 1
                for (int kd = 0; kd < K; kd++) {
#pragma unroll
                    for (int kh = 0; kh < K; kh++) {
                        const float* rp = s_slice + (dd + kd) * S2 + (hh + kh) * S;
                        float row[S];
#pragma unroll
                        for (int x = 0; x < S; x++) row[x] = rp[x];

                        float wr[COUT][K];
#pragma unroll
                        for (int co = 0; co < COUT; co++)
#pragma unroll
                            for (int kw = 0; kw < K; kw++)
                                wr[co][kw] = wb[co * CIN * KW4 + (kd * K + kh) * K + kw];

#pragma unroll
                        for (int kw = 0; kw < K; kw++)
#pragma unroll
                            for (int r = 0; r < O; r++)
#pragma unroll
                                for (int co = 0; co < COUT; co++)
                                    acc[co][r] = fmaf(wr[co][kw], row[r + kw], acc[co][r]);
                    }
                }
            }
        }
    }

    if (act) {
        const int t = t0 + tl;
#pragma unroll
        for (int co = 0; co < COUT; co++) {
            const float bv = bias[co];
            float* op = out + (size_t)(b * COUT + co) * ((size_t)O * O3)
                            + (size_t)t * O3 + (dd * O + hh) * O;
#pragma unroll
            for (int r = 0; r < O; r++)
                op[r] = fmaxf(acc[co][r] + bv, 0.0f);
        }
    }
}

// ===========================================================================
// FFMA2 row engine (convB family)
// ===========================================================================
template<int CO, int K, int RP, int COS>
__device__ __forceinline__ void row_r2(const float* __restrict__ rsrc,
                                       const float* __restrict__ wq,
                                       ull (&acc)[CO][RP])
{
    constexpr int RL = 2 * RP + K - 1;
    float row[RL];
#pragma unroll
    for (int x = 0; x < RL; x++) row[x] = rsrc[x];

    constexpr int NE = RP + 1;
    constexpr int NO = RP + (K >= 4 ? 1 : 0);
    ull rowE[NE], rowO[NO];
#pragma unroll
    for (int j = 0; j < NE; j++) rowE[j] = pk2(row[2 * j], row[2 * j + 1]);
#pragma unroll
    for (int j = 0; j < NO; j++) rowO[j] = pk2(row[2 * j + 1], row[2 * j + 2]);

#pragma unroll
    for (int kw = 0; kw < K; kw++) {
#pragma unroll
        for (int co = 0; co < CO; co++) {
            const float wv = wq[co * COS + kw];
            const ull w2 = pk2(wv, wv);
#pragma unroll
            for (int j = 0; j < RP; j++) {
                const ull a = (kw & 1) ? rowO[(kw >> 1) + j] : rowE[(kw >> 1) + j];
                fma2(acc[co][j], a, w2);
            }
        }
    }
}

// ===========================================================================
// convB: whole-volume FFMA2 conv (block = b, thread = (t,d,h)), double-
// buffered channel staging. FUSE_FC adds FC1+ReLU+FC2+sigmoid on the result.
// (L4: measured 124us across five rounds. L5+FC: passed in R2/R5 form.)
// ===========================================================================
template<int CIN, int COUT, int K, int S, int NTHR, bool FUSE_FC>
__global__ void __launch_bounds__(NTHR)
convB(const float* __restrict__ in, float* __restrict__ out,
      const float* __restrict__ w, const float* __restrict__ bias,
      const float* __restrict__ fc1w, const float* __restrict__ fc1b,
      const float* __restrict__ fc2w, const float* __restrict__ fc2b)
{
    constexpr int O = S - K + 1;
    constexpr int S2 = S * S, S3 = S2 * S, S4 = S3 * S;
    constexpr int O2 = O * O, O3 = O2 * O, O4 = O * O3;
    constexpr int K4 = K * K * K * K, NW = COUT * CIN * K4;
    constexpr int NACT = O * O2;
    constexpr int RP = (O + 1) / 2;
    constexpr int VP = slice_pitch(S4);
    constexpr int NF = COUT * O4;

    extern __shared__ float dsm[];           // 2 * VP
    __shared__ float s_w[NW];
    __shared__ float s_h[FUSE_FC ? NF : 1];
    __shared__ float s_so[FUSE_FC ? 33 : 1];

    const int b = blockIdx.x, tid = threadIdx.x;
    for (int i = tid; i < NW; i += NTHR) s_w[i] = w[i];

    const int tl = tid / O2, rem = tid - tl * O2, dd = rem / O, hh = rem - dd * O;
    const bool act = tid < NACT;

    ull acc[COUT][RP];
#pragma unroll
    for (int c = 0; c < COUT; c++)
#pragma unroll
        for (int j = 0; j < RP; j++) acc[c][j] = 0ull;

    {
        const float* src = in + (size_t)b * CIN * S4;
        for (int i = tid; i < S4; i += NTHR) dsm[i] = src[i];
    }
#pragma unroll 1
    for (int ci = 0; ci < CIN; ci++) {
        __syncthreads();
        if (ci + 1 < CIN) {
            const float* src = in + ((size_t)b * CIN + ci + 1) * S4;
            float* dst = dsm + ((ci + 1) & 1) * VP;
            for (int i = tid; i < S4; i += NTHR) dst[i] = src[i];
        }
        if (act) {
            const float* buf = dsm + (ci & 1) * VP;
#pragma unroll 1
            for (int kt = 0; kt < K; kt++) {
#pragma unroll 1
                for (int kd = 0; kd < K; kd++) {
#pragma unroll
                    for (int kh = 0; kh < K; kh++) {
                        const float* rp_ = buf + (tl + kt) * S3 + (dd + kd) * S2 + (hh + kh) * S;
                        const float* wq  = s_w + (((ci * K + kt) * K + kd) * K + kh) * K;
                        row_r2<COUT, K, RP, CIN * K4>(rp_, wq, acc);
                    }
                }
            }
        }
    }

    if (!FUSE_FC) {
        if (act) {
#pragma unroll
            for (int co = 0; co < COUT; co++) {
                const float bv = bias[co];
                float* op = out + ((size_t)b * COUT + co) * (size_t)O4
                                + (size_t)tl * O3 + (dd * O + hh) * O;
#pragma unroll
                for (int j = 0; j < RP; j++) {
                    float v0, v1; upk2(acc[co][j], v0, v1);
                    op[2 * j] = fmaxf(v0 + bv, 0.0f);
                    if (2 * j + 1 < O) op[2 * j + 1] = fmaxf(v1 + bv, 0.0f);
                }
            }
        }
    } else {
        if (act) {
#pragma unroll
            for (int co = 0; co < COUT; co++) {
                const float bv = bias[co];
                float* op = s_h + co * O4 + tl * O3 + (dd * O + hh) * O;
#pragma unroll
                for (int j = 0; j < RP; j++) {
                    float v0, v1; upk2(acc[co][j], v0, v1);
                    op[2 * j] = fmaxf(v0 + bv, 0.0f);
                    if (2 * j + 1 < O) op[2 * j + 1] = fmaxf(v1 + bv, 0.0f);
                }
            }
        }
        __syncthreads();
        if (tid < 33) {
            const float* wr = fc1w + tid * NF;
            float a0 = 0.f, a1 = 0.f, a2 = 0.f, a3 = 0.f;
#pragma unroll 4
            for (int k = 0; k < NF; k += 4) {
                a0 = fmaf(s_h[k + 0], __ldg(wr + k + 0), a0);
                a1 = fmaf(s_h[k + 1], __ldg(wr + k + 1), a1);
                a2 = fmaf(s_h[k + 2], __ldg(wr + k + 2), a2);
                a3 = fmaf(s_h[k + 3], __ldg(wr + k + 3), a3);
            }
            s_so[tid] = fmaxf((a0 + a1) + (a2 + a3) + fc1b[tid], 0.0f);
        }
        __syncthreads();
        if (tid == 0) {
            float z = fc2b[0];
#pragma unroll
            for (int j = 0; j < 33; j++) z = fmaf(s_so[j], __ldg(fc2w + j), z);
            out[b] = 1.0f / (1.0f + expf(-z));
        }
    }
}

// ---------------------------------------------------------------------------
// Inputs (metadata order):
// 0:x 1:w1 2:b1 3:w2 4:b2 5:w3 6:b3 7:w4 8:b4 9:w5 10:b5
// 11:fc1_w 12:fc1_b 13:fc2_w 14:fc2_b    -> out: [B,1] float32
// ---------------------------------------------------------------------------
extern "C" void kernel_launch(void* const* d_in, const int* in_sizes, int n_in,
                              void* d_out, int out_size)
{
    const float* x   = (const float*)d_in[0];
    const float* w1  = (const float*)d_in[1];
    const float* b1  = (const float*)d_in[2];
    const float* w2  = (const float*)d_in[3];
    const float* b2  = (const float*)d_in[4];
    const float* w3  = (const float*)d_in[5];
    const float* b3  = (const float*)d_in[6];
    const float* w4  = (const float*)d_in[7];
    const float* b4  = (const float*)d_in[8];
    const float* w5  = (const float*)d_in[9];
    const float* b5  = (const float*)d_in[10];
    const float* f1w = (const float*)d_in[11];
    const float* f1b = (const float*)d_in[12];
    const float* f2w = (const float*)d_in[13];
    const float* f2b = (const float*)d_in[14];

    const int B = in_sizes[0] / (18 * 18 * 18 * 18);

    float *a1, *a2, *a3, *a4;
    cudaGetSymbolAddress((void**)&a1, g_a1);
    cudaGetSymbolAddress((void**)&a2, g_a2);
    cudaGetSymbolAddress((void**)&a3, g_a3);
    cudaGetSymbolAddress((void**)&a4, g_a4);

    constexpr int SM4 = 2 * slice_pitch(9 * 9 * 9 * 9) * 4;      // 52528 B
    constexpr int SM5 = 2 * slice_pitch(6 * 6 * 6 * 6) * 4;      // 10416 B

    cudaFuncSetAttribute(convB<4, 5, 4, 9, 224, false>,
                         cudaFuncAttributeMaxDynamicSharedMemorySize, SM4);
    cudaFuncSetAttribute(convB<5, 5, 3, 6, 128, true>,
                         cudaFuncAttributeMaxDynamicSharedMemorySize, SM5);

    // L1: 18^4 -> 15^4, 1->3, k=4   (R1 exact: grid 3840, 225/256 active)
    convS<1, 3, 4, 18, 1, 256, 2><<<B * 15, 256>>>(x,  a1, w1, b1);
    // L2: 15^4 -> 12^4, 3->3, k=4   (R1 exact: grid 3072, 144/256 active)
    convS<3, 3, 4, 15, 1, 256, 2><<<B * 12, 256>>>(a1, a2, w2, b2);
    // L3: 12^4 -> 9^4, 3->4, k=4    (R1 exact: grid 768, 243/256 active)
    convS<3, 4, 4, 12, 3, 256, 2><<<B * 3, 256>>>(a2, a3, w3, b3);
    // L4: 9^4 -> 6^4, 4->5, k=4     (convB, measured 124us x5)
    convB<4, 5, 4, 9, 224, false><<<B, 224, SM4>>>(a3, a4, w4, b4,
                                                   nullptr, nullptr, nullptr, nullptr);
    // L5: 6^4 -> 4^4, 5->5, k=3 + fused FC1/ReLU/FC2/sigmoid -> d_out [B,1]
    convB<5, 5, 3, 6, 128, true><<<B, 128, SM5>>>(a4, (float*)d_out, w5, b5,
                                                  f1w, f1b, f2w, f2b);
}

// round 12
// speedup vs baseline: 1.0948x; 1.0948x over previous
#include <cuda_runtime.h>
#include <math.h>

typedef unsigned long long ull;

// ---------------------------------------------------------------------------
// Packed f32x2 helpers (convB only — measured fastest for L4)
// ---------------------------------------------------------------------------
__device__ __forceinline__ ull pk2(float lo, float hi) {
    ull r; asm("mov.b64 %0, {%1, %2};" : "=l"(r) : "f"(lo), "f"(hi)); return r;
}
__device__ __forceinline__ void upk2(ull v, float& lo, float& hi) {
    asm("mov.b64 {%0, %1}, %2;" : "=f"(lo), "=f"(hi) : "l"(v));
}
__device__ __forceinline__ void fma2(ull& d, ull a, ull b) {
    asm("fma.rn.f32x2 %0, %1, %2, %0;" : "+l"(d) : "l"(a), "l"(b));
}

// ---------------------------------------------------------------------------
// Intermediate activation buffers (device globals — no allocation allowed).
// ---------------------------------------------------------------------------
__device__ float g_a1[38880000];   // 256*3*15^4
__device__ float g_a2[15925248];   // 256*3*12^4
__device__ float g_a3[6718464];    // 256*4*9^4
__device__ float g_a4[1658880];    // 256*5*6^4
__device__ float g_a5[327680];     // 256*5*4^4  (== flattened [256,1280])

__host__ __device__ constexpr int slice_pitch(int s3) { return (s3 + 6) & ~1; }

// ===========================================================================
// convS: R1's proven full-row scalar conv (+bias+ReLU). Block = (b, t-chunk).
// Thread = (t_local, d, h) computes the full W row for all COUT.
// ===========================================================================
template<int CIN, int COUT, int K, int S, int TLOC, int NTHR>
__global__ void __launch_bounds__(NTHR)
convS(const float* __restrict__ in, float* __restrict__ out,
      const float* __restrict__ w, const float* __restrict__ bias)
{
    constexpr int O = S - K + 1, TCH = O / TLOC, NST = TLOC + K - 1;
    constexpr int S2 = S * S, S3 = S2 * S, S4 = S3 * S;
    constexpr int O2 = O * O, O3 = O2 * O;
    constexpr int KW4 = K * K * K * K;
    constexpr int NW = COUT * CIN * KW4;
    constexpr int NACT = TLOC * O2;

    __shared__ float s_slice[S3];
    __shared__ float s_w[NW];

    const int bt = blockIdx.x, tchunk = bt % TCH, b = bt / TCH;
    const int t0 = tchunk * TLOC, tid = threadIdx.x;

    for (int i = tid; i < NW; i += NTHR) s_w[i] = w[i];

    const int tl = tid / O2, rem = tid - tl * O2, dd = rem / O, hh = rem - dd * O;
    const bool act = tid < NACT;

    float acc[COUT][O];
#pragma unroll
    for (int c = 0; c < COUT; c++)
#pragma unroll
        for (int r = 0; r < O; r++) acc[c][r] = 0.0f;

#pragma unroll 1
    for (int ci = 0; ci < CIN; ci++) {
#pragma unroll 1
        for (int s = 0; s < NST; s++) {
            __syncthreads();
            const float* src = in + (size_t)(b * CIN + ci) * S4 + (size_t)(t0 + s) * S3;
            for (int i = tid; i < S3; i += NTHR) s_slice[i] = src[i];
            __syncthreads();

            const int kt = s - tl;
            if (act && kt >= 0 && kt < K) {
                const float* wb = s_w + (ci * K + kt) * (K * K * K);
#pragma unroll 1
                for (int kd = 0; kd < K; kd++) {
#pragma unroll
                    for (int kh = 0; kh < K; kh++) {
                        const float* rp = s_slice + (dd + kd) * S2 + (hh + kh) * S;
                        float row[S];
#pragma unroll
                        for (int x = 0; x < S; x++) row[x] = rp[x];

                        float wr[COUT][K];
#pragma unroll
                        for (int co = 0; co < COUT; co++)
#pragma unroll
                            for (int kw = 0; kw < K; kw++)
                                wr[co][kw] = wb[co * CIN * KW4 + (kd * K + kh) * K + kw];

#pragma unroll
                        for (int kw = 0; kw < K; kw++)
#pragma unroll
                            for (int r = 0; r < O; r++)
#pragma unroll
                                for (int co = 0; co < COUT; co++)
                                    acc[co][r] = fmaf(wr[co][kw], row[r + kw], acc[co][r]);
                    }
                }
            }
        }
    }

    if (act) {
        const int t = t0 + tl;
#pragma unroll
        for (int co = 0; co < COUT; co++) {
            const float bv = bias[co];
            float* op = out + (size_t)(b * COUT + co) * ((size_t)O * O3)
                            + (size_t)t * O3 + (dd * O + hh) * O;
#pragma unroll
            for (int r = 0; r < O; r++)
                op[r] = fmaxf(acc[co][r] + bv, 0.0f);
        }
    }
}

// ===========================================================================
// FFMA2 row engine (convB only)
// ===========================================================================
template<int CO, int K, int RP, int COS>
__device__ __forceinline__ void row_r2(const float* __restrict__ rsrc,
                                       const float* __restrict__ wq,
                                       ull (&acc)[CO][RP])
{
    constexpr int RL = 2 * RP + K - 1;
    float row[RL];
#pragma unroll
    for (int x = 0; x < RL; x++) row[x] = rsrc[x];

    constexpr int NE = RP + 1;
    constexpr int NO = RP + (K >= 4 ? 1 : 0);
    ull rowE[NE], rowO[NO];
#pragma unroll
    for (int j = 0; j < NE; j++) rowE[j] = pk2(row[2 * j], row[2 * j + 1]);
#pragma unroll
    for (int j = 0; j < NO; j++) rowO[j] = pk2(row[2 * j + 1], row[2 * j + 2]);

#pragma unroll
    for (int kw = 0; kw < K; kw++) {
#pragma unroll
        for (int co = 0; co < CO; co++) {
            const float wv = wq[co * COS + kw];
            const ull w2 = pk2(wv, wv);
#pragma unroll
            for (int j = 0; j < RP; j++) {
                const ull a = (kw & 1) ? rowO[(kw >> 1) + j] : rowE[(kw >> 1) + j];
                fma2(acc[co][j], a, w2);
            }
        }
    }
}

// ===========================================================================
// convB (measured-fastest L4, unchanged): whole-volume FFMA2 conv, block = b,
// thread = (t,d,h), double-buffered channel staging.
// ===========================================================================
template<int CIN, int COUT, int K, int S, int NTHR>
__global__ void __launch_bounds__(NTHR)
convB(const float* __restrict__ in, float* __restrict__ out,
      const float* __restrict__ w, const float* __restrict__ bias)
{
    constexpr int O = S - K + 1;
    constexpr int S2 = S * S, S3 = S2 * S, S4 = S3 * S;
    constexpr int O2 = O * O, O3 = O2 * O, O4 = O * O3;
    constexpr int K4 = K * K * K * K, NW = COUT * CIN * K4;
    constexpr int NACT = O * O2;
    constexpr int RP = (O + 1) / 2;
    constexpr int VP = slice_pitch(S4);

    extern __shared__ float dsm[];           // 2 * VP
    __shared__ float s_w[NW];

    const int b = blockIdx.x, tid = threadIdx.x;
    for (int i = tid; i < NW; i += NTHR) s_w[i] = w[i];

    const int tl = tid / O2, rem = tid - tl * O2, dd = rem / O, hh = rem - dd * O;
    const bool act = tid < NACT;

    ull acc[COUT][RP];
#pragma unroll
    for (int c = 0; c < COUT; c++)
#pragma unroll
        for (int j = 0; j < RP; j++) acc[c][j] = 0ull;

    {
        const float* src = in + (size_t)b * CIN * S4;
        for (int i = tid; i < S4; i += NTHR) dsm[i] = src[i];
    }
#pragma unroll 1
    for (int ci = 0; ci < CIN; ci++) {
        __syncthreads();
        if (ci + 1 < CIN) {
            const float* src = in + ((size_t)b * CIN + ci + 1) * S4;
            float* dst = dsm + ((ci + 1) & 1) * VP;
            for (int i = tid; i < S4; i += NTHR) dst[i] = src[i];
        }
        if (act) {
            const float* buf = dsm + (ci & 1) * VP;
#pragma unroll 1
            for (int kt = 0; kt < K; kt++) {
#pragma unroll 1
                for (int kd = 0; kd < K; kd++) {
#pragma unroll
                    for (int kh = 0; kh < K; kh++) {
                        const float* rp_ = buf + (tl + kt) * S3 + (dd + kd) * S2 + (hh + kh) * S;
                        const float* wq  = s_w + (((ci * K + kt) * K + kd) * K + kh) * K;
                        row_r2<COUT, K, RP, CIN * K4>(rp_, wq, acc);
                    }
                }
            }
        }
    }

    if (act) {
#pragma unroll
        for (int co = 0; co < COUT; co++) {
            const float bv = bias[co];
            float* op = out + ((size_t)b * COUT + co) * (size_t)O4
                            + (size_t)tl * O3 + (dd * O + hh) * O;
#pragma unroll
            for (int j = 0; j < RP; j++) {
                float v0, v1; upk2(acc[co][j], v0, v1);
                op[2 * j] = fmaxf(v0 + bv, 0.0f);
                if (2 * j + 1 < O) op[2 * j + 1] = fmaxf(v1 + bv, 0.0f);
            }
        }
    }
}

// ---------------------------------------------------------------------------
// Fused FC1(1280->33) + ReLU + FC2(33->1) + sigmoid. One block per batch row.
// (R1's proven head — kept SEPARATE; fusing into L5 measured +175us in R11.)
// ---------------------------------------------------------------------------
__global__ void __launch_bounds__(64)
fc_head(const float* __restrict__ h,
        const float* __restrict__ fc1w, const float* __restrict__ fc1b,
        const float* __restrict__ fc2w, const float* __restrict__ fc2b,
        float* __restrict__ out)
{
    __shared__ float sh[1280];
    __shared__ float so[33];
    const int b = blockIdx.x;

    for (int i = threadIdx.x; i < 1280; i += 64) sh[i] = h[(size_t)b * 1280 + i];
    __syncthreads();

    const int co = threadIdx.x;
    if (co < 33) {
        float a = 0.0f;
        const float* wr = fc1w + co * 1280;
#pragma unroll 4
        for (int k = 0; k < 1280; k++) a = fmaf(sh[k], __ldg(&wr[k]), a);
        so[co] = fmaxf(a + fc1b[co], 0.0f);
    }
    __syncthreads();

    if (threadIdx.x == 0) {
        float z = fc2b[0];
#pragma unroll
        for (int j = 0; j < 33; j++) z = fmaf(so[j], __ldg(&fc2w[j]), z);
        out[b] = 1.0f / (1.0f + expf(-z));
    }
}

// ---------------------------------------------------------------------------
// Inputs (metadata order):
// 0:x 1:w1 2:b1 3:w2 4:b2 5:w3 6:b3 7:w4 8:b4 9:w5 10:b5
// 11:fc1_w 12:fc1_b 13:fc2_w 14:fc2_b    -> out: [B,1] float32
// ---------------------------------------------------------------------------
extern "C" void kernel_launch(void* const* d_in, const int* in_sizes, int n_in,
                              void* d_out, int out_size)
{
    const float* x   = (const float*)d_in[0];
    const float* w1  = (const float*)d_in[1];
    const float* b1  = (const float*)d_in[2];
    const float* w2  = (const float*)d_in[3];
    const float* b2  = (const float*)d_in[4];
    const float* w3  = (const float*)d_in[5];
    const float* b3  = (const float*)d_in[6];
    const float* w4  = (const float*)d_in[7];
    const float* b4  = (const float*)d_in[8];
    const float* w5  = (const float*)d_in[9];
    const float* b5  = (const float*)d_in[10];
    const float* f1w = (const float*)d_in[11];
    const float* f1b = (const float*)d_in[12];
    const float* f2w = (const float*)d_in[13];
    const float* f2b = (const float*)d_in[14];

    const int B = in_sizes[0] / (18 * 18 * 18 * 18);

    float *a1, *a2, *a3, *a4, *a5;
    cudaGetSymbolAddress((void**)&a1, g_a1);
    cudaGetSymbolAddress((void**)&a2, g_a2);
    cudaGetSymbolAddress((void**)&a3, g_a3);
    cudaGetSymbolAddress((void**)&a4, g_a4);
    cudaGetSymbolAddress((void**)&a5, g_a5);

    constexpr int SM4 = 2 * slice_pitch(9 * 9 * 9 * 9) * 4;      // 52528 B

    cudaFuncSetAttribute(convB<4, 5, 4, 9, 224>,
                         cudaFuncAttributeMaxDynamicSharedMemorySize, SM4);

    // L1: 18^4 -> 15^4, 1->3, k=4   (R1 exact: grid 3840, 225/256 active)
    convS<1, 3, 4, 18, 1, 256><<<B * 15, 256>>>(x,  a1, w1, b1);
    // L2: 15^4 -> 12^4, 3->3, k=4   (R1 exact: grid 3072, 144/256 active)
    convS<3, 3, 4, 15, 1, 256><<<B * 12, 256>>>(a1, a2, w2, b2);
    // L3: 12^4 -> 9^4, 3->4, k=4    (R1 exact: grid 768, 243/256 active)
    convS<3, 4, 4, 12, 3, 256><<<B * 3, 256>>>(a2, a3, w3, b3);
    // L4: 9^4 -> 6^4, 4->5, k=4     (convB, measured ~124us six times)
    convB<4, 5, 4, 9, 224><<<B, 224, SM4>>>(a3, a4, w4, b4);
    // L5: 6^4 -> 4^4, 5->5, k=3     (R1 exact)
    convS<5, 5, 3, 6, 4, 128><<<B, 128>>>(a4, a5, w5, b5);
    // FC head: [B,1280] -> [B,33] -> [B,1] sigmoid (R1 exact, separate)
    fc_head<<<B, 64>>>(a5, f1w, f1b, f2w, f2b, (float*)d_out);
}